// round 4
// baseline (speedup 1.0000x reference)
#include <cuda_runtime.h>
#include <cuda_fp16.h>
#include <cstdint>

// ======================= problem constants =======================
static constexpr int K_DIM  = 2048;
static constexpr int N_ROWS = 8192;
static constexpr int M_TOK  = 8192;
static constexpr int N_OUT  = 4096;

// ======================= GEMM tiling =============================
static constexpr int BM = 128;          // token rows per CTA tile
static constexpr int BNR = 256;         // B rows per CTA tile = 128 h + 128 g
static constexpr int BK = 64;
static constexpr int CHUNKS_PER_TILE = K_DIM / BK;     // 32
static constexpr int NSTAGE = 3;
static constexpr int A_BYTES = BM * BK * 2;            // 16384
static constexpr int B_BYTES = BNR * BK * 2;           // 32768
static constexpr int STAGE_BYTES = A_BYTES + B_BYTES;  // 49152
static constexpr int SMEM_TOTAL = NSTAGE * STAGE_BYTES; // 147456
static constexpr int M_TILES = M_TOK / BM;             // 64
static constexpr int N_TILES = N_OUT / 128;            // 32 (128 out cols per tile)
static constexpr int TOTAL_TILES = M_TILES * N_TILES;  // 2048

// ======================= device scratch ==========================
__device__ float  g55_partial[2048];
__device__ float  g55_wgamma;
__device__ __half g55_wbin[(size_t)N_ROWS * K_DIM];
__device__ __half g55_act [(size_t)M_TOK  * K_DIM];

struct __align__(16) H8 { __half2 a, b, c, d; };

// ======================= asm helpers =============================
__device__ __forceinline__ uint32_t smem_u32(const void* p) {
    uint32_t a;
    asm("{ .reg .u64 t; cvta.to.shared.u64 t, %1; cvt.u32.u64 %0, t; }" : "=r"(a) : "l"(p));
    return a;
}

#define CP_ASYNC16(dst_u32, src_ptr) \
    asm volatile("cp.async.cg.shared.global [%0], [%1], 16;" \
                 :: "r"(dst_u32), "l"(src_ptr) : "memory")

#define CP_COMMIT() asm volatile("cp.async.commit_group;" ::: "memory")
#define CP_WAIT(n)  asm volatile("cp.async.wait_group %0;" :: "n"(n) : "memory")

#define LDSM_X4(r0, r1, r2, r3, addr) \
    asm volatile("ldmatrix.sync.aligned.m8n8.x4.shared.b16 {%0,%1,%2,%3}, [%4];" \
                 : "=r"(r0), "=r"(r1), "=r"(r2), "=r"(r3) : "r"(addr))

#define MMA16816(d, a0, a1, a2, a3, b0, b1) \
    asm volatile("mma.sync.aligned.m16n8k16.row.col.f32.f16.f16.f32 " \
                 "{%0,%1,%2,%3}, {%4,%5,%6,%7}, {%8,%9}, {%0,%1,%2,%3};" \
                 : "+f"((d)[0]), "+f"((d)[1]), "+f"((d)[2]), "+f"((d)[3]) \
                 : "r"(a0), "r"(a1), "r"(a2), "r"(a3), "r"(b0), "r"(b1))

__device__ __forceinline__ float warp_sum(float v) {
#pragma unroll
    for (int o = 16; o; o >>= 1) v += __shfl_xor_sync(0xffffffffu, v, o);
    return v;
}

// ======================= prep kernels (R2 proven) =================

__global__ __launch_bounds__(256) void glu55_wabs_partial(const float* __restrict__ w) {
    const int tid = threadIdx.x;
    const float4* w4 = reinterpret_cast<const float4*>(w);
    float s = 0.0f;
    int idx = blockIdx.x * 256 + tid;
#pragma unroll
    for (int i = 0; i < 8; ++i) {
        float4 v = w4[idx + i * (2048 * 256)];
        s += fabsf(v.x) + fabsf(v.y) + fabsf(v.z) + fabsf(v.w);
    }
    s = warp_sum(s);
    __shared__ float sh[8];
    if ((tid & 31) == 0) sh[tid >> 5] = s;
    __syncthreads();
    if (tid == 0) {
        float t = 0.0f;
#pragma unroll
        for (int i = 0; i < 8; ++i) t += sh[i];
        g55_partial[blockIdx.x] = t;
    }
}

__global__ __launch_bounds__(256) void glu55_wabs_final() {
    const int tid = threadIdx.x;
    float s = 0.0f;
    for (int i = tid; i < 2048; i += 256) s += g55_partial[i];
    s = warp_sum(s);
    __shared__ float sh[8];
    if ((tid & 31) == 0) sh[tid >> 5] = s;
    __syncthreads();
    if (tid == 0) {
        float t = 0.0f;
#pragma unroll
        for (int i = 0; i < 8; ++i) t += sh[i];
        g55_wgamma = t / (float)((size_t)N_ROWS * K_DIM);
    }
}

__device__ __forceinline__ float tern1(float v, float inv) {
    float r = rintf(v * inv);
    return fminf(1.0f, fmaxf(-1.0f, r));
}

__global__ __launch_bounds__(256) void glu55_tern(const float* __restrict__ w) {
    const int gid = blockIdx.x * 256 + threadIdx.x;
    const float inv = 1.0f / (g55_wgamma + 1e-7f);
    const float4* w4 = reinterpret_cast<const float4*>(w);
    float4 a = w4[gid * 2 + 0];
    float4 b = w4[gid * 2 + 1];
    H8 o;
    o.a = __floats2half2_rn(tern1(a.x, inv), tern1(a.y, inv));
    o.b = __floats2half2_rn(tern1(a.z, inv), tern1(a.w, inv));
    o.c = __floats2half2_rn(tern1(b.x, inv), tern1(b.y, inv));
    o.d = __floats2half2_rn(tern1(b.z, inv), tern1(b.w, inv));
    reinterpret_cast<H8*>(g55_wbin)[gid] = o;
}

__global__ __launch_bounds__(256) void glu55_ln(const float* __restrict__ x) {
    const int row = blockIdx.x;
    const int tid = threadIdx.x;
    const float4* xr = reinterpret_cast<const float4*>(x + (size_t)row * K_DIM);
    float4 v0 = xr[tid * 2 + 0];
    float4 v1 = xr[tid * 2 + 1];
    float s = v0.x + v0.y + v0.z + v0.w + v1.x + v1.y + v1.z + v1.w;
    float q = v0.x * v0.x + v0.y * v0.y + v0.z * v0.z + v0.w * v0.w +
              v1.x * v1.x + v1.y * v1.y + v1.z * v1.z + v1.w * v1.w;
    s = warp_sum(s);
    q = warp_sum(q);
    __shared__ float sh[18];
    const int wid = tid >> 5, lid = tid & 31;
    if (lid == 0) { sh[wid] = s; sh[8 + wid] = q; }
    __syncthreads();
    if (tid == 0) {
        float S = 0.0f, Q = 0.0f;
#pragma unroll
        for (int i = 0; i < 8; ++i) { S += sh[i]; Q += sh[8 + i]; }
        float mu  = S * (1.0f / (float)K_DIM);
        float var = Q * (1.0f / (float)K_DIM) - mu * mu;
        sh[16] = mu;
        sh[17] = rsqrtf(var + 1e-5f);
    }
    __syncthreads();
    const float mu = sh[16], rs = sh[17];
    H8 o;
    o.a = __floats2half2_rn((v0.x - mu) * rs, (v0.y - mu) * rs);
    o.b = __floats2half2_rn((v0.z - mu) * rs, (v0.w - mu) * rs);
    o.c = __floats2half2_rn((v1.x - mu) * rs, (v1.y - mu) * rs);
    o.d = __floats2half2_rn((v1.z - mu) * rs, (v1.w - mu) * rs);
    reinterpret_cast<H8*>(g55_act)[(size_t)row * (K_DIM / 8) + tid] = o;
}

// ======================= persistent GEMM + fused GLU =============
// grid = #SMs, 1 CTA/SM (144KB smem). Each CTA processes tiles
// id = bid, bid+grid, ... < 2048;  tile id -> mT = id & 63, nT = id >> 6.
// 8 warps: wm = wid&1 (m64), ngrp = wid>>1 (32 h rows + 32 g rows each).
// Global chunk stream g = tile*32 + c; stage = g % 3 (pipeline crosses tiles).

__global__ void __launch_bounds__(256, 1) glu55_gemm(
    const __half* __restrict__ A, const __half* __restrict__ B,
    float* __restrict__ out)
{
    extern __shared__ char smem[];
    const uint32_t sbase = smem_u32(smem);
    const int tid  = threadIdx.x;
    const int lane = tid & 31;
    const int wid  = tid >> 5;
    const int wm   = wid & 1;
    const int ngrp = wid >> 1;
    const int bid  = blockIdx.x;
    const int grid = gridDim.x;

    const int ntiles = (bid < TOTAL_TILES) ? ((TOTAL_TILES - 1 - bid) / grid + 1) : 0;
    const int total  = ntiles * CHUNKS_PER_TILE;
    if (total == 0) return;

    float ah[4][4][4], ag[4][4][4];
#pragma unroll
    for (int i = 0; i < 4; ++i)
#pragma unroll
        for (int j = 0; j < 4; ++j)
#pragma unroll
            for (int k = 0; k < 4; ++k) { ah[i][j][k] = 0.0f; ag[i][j][k] = 0.0f; }

    const int ld_row = tid >> 3;   // 0..31
    const int ld_ch  = tid & 7;    // 16B chunk within 128B row

    // issue loads for global chunk g into stage g%3
    auto issue_stage = [&](int g) {
        const int t  = g >> 5;                 // local tile index
        const int id = bid + t * grid;         // global tile id
        const int mT = id & 63;
        const int nT = id >> 6;
        const int k0 = (g & 31) * BK;
        const uint32_t sA = sbase + (g % NSTAGE) * STAGE_BYTES;
        const uint32_t sB = sA + A_BYTES;
        const __half* gAr = A + (size_t)(mT * BM) * K_DIM + k0;
#pragma unroll
        for (int it = 0; it < 4; ++it) {
            const int row = it * 32 + ld_row;
            const __half* src = gAr + (size_t)row * K_DIM + ld_ch * 8;
            CP_ASYNC16(sA + row * 128 + ((ld_ch ^ (row & 7)) << 4), src);
        }
        const __half* gBr = B + (size_t)(nT * 128) * K_DIM + k0;
#pragma unroll
        for (int it = 0; it < 8; ++it) {
            const int row = it * 32 + ld_row;          // 0..255
            // rows 0..127 = h (W rows nT*128+row), 128..255 = g (+4096 rows)
            const size_t grow = (size_t)(row & 127) + ((size_t)(row >> 7) << 12);
            const __half* src = gBr + grow * K_DIM + ld_ch * 8;
            CP_ASYNC16(sB + row * 128 + ((ld_ch ^ (row & 7)) << 4), src);
        }
        CP_COMMIT();
    };

    auto compute_stage = [&](int st) {
        const uint32_t sA = sbase + st * STAGE_BYTES;
        const uint32_t sB = sA + A_BYTES;
#pragma unroll
        for (int kk = 0; kk < 4; ++kk) {
            uint32_t a[4][4];
#pragma unroll
            for (int mt = 0; mt < 4; ++mt) {
                const int row = wm * 64 + mt * 16 + (lane & 15);
                const int ch  = kk * 2 + (lane >> 4);
                LDSM_X4(a[mt][0], a[mt][1], a[mt][2], a[mt][3],
                        sA + row * 128 + ((ch ^ (row & 7)) << 4));
            }
            uint32_t bh[2][4], bg[2][4];
#pragma unroll
            for (int tp = 0; tp < 2; ++tp) {
                const int rb = ngrp * 32 + tp * 16 + ((lane >> 4) << 3) + (lane & 7);
                const int ch = kk * 2 + ((lane >> 3) & 1);
                const uint32_t sw = ((ch ^ (rb & 7)) << 4);
                LDSM_X4(bh[tp][0], bh[tp][1], bh[tp][2], bh[tp][3], sB + rb * 128 + sw);
                LDSM_X4(bg[tp][0], bg[tp][1], bg[tp][2], bg[tp][3], sB + (rb + 128) * 128 + sw);
            }
#pragma unroll
            for (int mt = 0; mt < 4; ++mt)
#pragma unroll
                for (int tp = 0; tp < 2; ++tp) {
                    MMA16816(ah[mt][2 * tp + 0], a[mt][0], a[mt][1], a[mt][2], a[mt][3], bh[tp][0], bh[tp][1]);
                    MMA16816(ah[mt][2 * tp + 1], a[mt][0], a[mt][1], a[mt][2], a[mt][3], bh[tp][2], bh[tp][3]);
                    MMA16816(ag[mt][2 * tp + 0], a[mt][0], a[mt][1], a[mt][2], a[mt][3], bg[tp][0], bg[tp][1]);
                    MMA16816(ag[mt][2 * tp + 1], a[mt][0], a[mt][1], a[mt][2], a[mt][3], bg[tp][2], bg[tp][3]);
                }
        }
    };

    const float gw = g55_wgamma;

    issue_stage(0);
    if (total > 1) issue_stage(1); else CP_COMMIT();

    for (int g = 0; g < total; ++g) {
        CP_WAIT(1);
        __syncthreads();
        compute_stage(g % NSTAGE);
        if (g + 2 < total) issue_stage(g + 2);
        else CP_COMMIT();

        if ((g & 31) == 31) {
            // ---- fused GLU epilogue for tile (g>>5), overlaps next loads ----
            const int id = bid + (g >> 5) * grid;
            const int mT = id & 63;
            const int nT = id >> 6;
            const int row0 = mT * BM + wm * 64 + (lane >> 2);
            const int col0 = nT * 128 + ngrp * 32 + 2 * (lane & 3);
#pragma unroll
            for (int mt = 0; mt < 4; ++mt)
#pragma unroll
                for (int nb = 0; nb < 4; ++nb)
#pragma unroll
                    for (int hf = 0; hf < 2; ++hf) {
                        const float h0 = ah[mt][nb][2 * hf + 0] * gw;
                        const float h1 = ah[mt][nb][2 * hf + 1] * gw;
                        const float g0 = ag[mt][nb][2 * hf + 0] * gw;
                        const float g1 = ag[mt][nb][2 * hf + 1] * gw;
                        float2 o;
                        o.x = h0 * (g0 / (1.0f + __expf(-g0)));
                        o.y = h1 * (g1 / (1.0f + __expf(-g1)));
                        const int r = row0 + mt * 16 + hf * 8;
                        *reinterpret_cast<float2*>(out + (size_t)r * N_OUT + col0 + nb * 8) = o;
                        ah[mt][nb][2 * hf + 0] = 0.0f; ah[mt][nb][2 * hf + 1] = 0.0f;
                        ag[mt][nb][2 * hf + 0] = 0.0f; ag[mt][nb][2 * hf + 1] = 0.0f;
                    }
        }
    }
}

// ======================= host launcher ===========================

extern "C" void kernel_launch(void* const* d_in, const int* in_sizes, int n_in,
                              void* d_out, int out_size) {
    (void)in_sizes; (void)n_in; (void)out_size;
    const float* x = (const float*)d_in[0];
    const float* w = (const float*)d_in[1];
    float* out = (float*)d_out;

    void *p_wbin = nullptr, *p_act = nullptr;
    cudaGetSymbolAddress(&p_wbin, g55_wbin);
    cudaGetSymbolAddress(&p_act,  g55_act);

    glu55_wabs_partial<<<2048, 256>>>(w);
    glu55_wabs_final<<<1, 256>>>();
    glu55_tern<<<8192, 256>>>(w);
    glu55_ln<<<M_TOK, 256>>>(x);

    int nsm = 148;
    cudaDeviceGetAttribute(&nsm, cudaDevAttrMultiProcessorCount, 0);

    cudaFuncSetAttribute(glu55_gemm, cudaFuncAttributeMaxDynamicSharedMemorySize, SMEM_TOTAL);
    glu55_gemm<<<nsm, 256, SMEM_TOTAL>>>(
        (const __half*)p_act, (const __half*)p_wbin, out);
}

// round 6
// speedup vs baseline: 1.0248x; 1.0248x over previous
#include <cuda_runtime.h>
#include <cuda_fp16.h>
#include <cstdint>

// ======================= problem constants =======================
static constexpr int K_DIM  = 2048;
static constexpr int N_ROWS = 8192;
static constexpr int M_TOK  = 8192;
static constexpr int N_OUT  = 4096;

// ======================= GEMM tiling (R2-proven) =================
static constexpr int BM = 128;        // token rows per CTA tile
static constexpr int BK = 64;         // K per stage
static constexpr int CHUNKS_PER_TILE = K_DIM / BK;       // 32
static constexpr int NSTAGE = 3;
static constexpr int TILE_BYTES  = BM * BK * 2;          // 16384
static constexpr int STAGE_BYTES = 2 * TILE_BYTES;       // A + B = 32768
static constexpr int SMEM_TOTAL  = NSTAGE * STAGE_BYTES; // 98304
static constexpr int M_TILES = M_TOK / BM;               // 64
static constexpr int N_TILES = N_OUT / 64;               // 64
static constexpr int TOTAL_TILES = M_TILES * N_TILES;    // 4096

// ======================= device scratch ==========================
__device__ float  g55_partial[2048];
__device__ float  g55_wgamma;
__device__ __half g55_wbin[(size_t)N_ROWS * K_DIM];
__device__ __half g55_act [(size_t)M_TOK  * K_DIM];

struct __align__(16) H8 { __half2 a, b, c, d; };

// ======================= asm helpers =============================
__device__ __forceinline__ uint32_t smem_u32(const void* p) {
    uint32_t a;
    asm("{ .reg .u64 t; cvta.to.shared.u64 t, %1; cvt.u32.u64 %0, t; }" : "=r"(a) : "l"(p));
    return a;
}

#define CP_ASYNC16(dst_u32, src_ptr) \
    asm volatile("cp.async.cg.shared.global [%0], [%1], 16;" \
                 :: "r"(dst_u32), "l"(src_ptr) : "memory")

#define CP_COMMIT() asm volatile("cp.async.commit_group;" ::: "memory")
#define CP_WAIT(n)  asm volatile("cp.async.wait_group %0;" :: "n"(n) : "memory")

#define LDSM_X4(r0, r1, r2, r3, addr) \
    asm volatile("ldmatrix.sync.aligned.m8n8.x4.shared.b16 {%0,%1,%2,%3}, [%4];" \
                 : "=r"(r0), "=r"(r1), "=r"(r2), "=r"(r3) : "r"(addr))

#define MMA16816(d, a0, a1, a2, a3, b0, b1) \
    asm volatile("mma.sync.aligned.m16n8k16.row.col.f32.f16.f16.f32 " \
                 "{%0,%1,%2,%3}, {%4,%5,%6,%7}, {%8,%9}, {%0,%1,%2,%3};" \
                 : "+f"((d)[0]), "+f"((d)[1]), "+f"((d)[2]), "+f"((d)[3]) \
                 : "r"(a0), "r"(a1), "r"(a2), "r"(a3), "r"(b0), "r"(b1))

__device__ __forceinline__ float warp_sum(float v) {
#pragma unroll
    for (int o = 16; o; o >>= 1) v += __shfl_xor_sync(0xffffffffu, v, o);
    return v;
}

// ======================= prep kernels (R2 proven, unchanged) ======

__global__ __launch_bounds__(256) void glu55_wabs_partial(const float* __restrict__ w) {
    const int tid = threadIdx.x;
    const float4* w4 = reinterpret_cast<const float4*>(w);
    float s = 0.0f;
    int idx = blockIdx.x * 256 + tid;
#pragma unroll
    for (int i = 0; i < 8; ++i) {
        float4 v = w4[idx + i * (2048 * 256)];
        s += fabsf(v.x) + fabsf(v.y) + fabsf(v.z) + fabsf(v.w);
    }
    s = warp_sum(s);
    __shared__ float sh[8];
    if ((tid & 31) == 0) sh[tid >> 5] = s;
    __syncthreads();
    if (tid == 0) {
        float t = 0.0f;
#pragma unroll
        for (int i = 0; i < 8; ++i) t += sh[i];
        g55_partial[blockIdx.x] = t;
    }
}

__global__ __launch_bounds__(256) void glu55_wabs_final() {
    const int tid = threadIdx.x;
    float s = 0.0f;
    for (int i = tid; i < 2048; i += 256) s += g55_partial[i];
    s = warp_sum(s);
    __shared__ float sh[8];
    if ((tid & 31) == 0) sh[tid >> 5] = s;
    __syncthreads();
    if (tid == 0) {
        float t = 0.0f;
#pragma unroll
        for (int i = 0; i < 8; ++i) t += sh[i];
        g55_wgamma = t / (float)((size_t)N_ROWS * K_DIM);
    }
}

__device__ __forceinline__ float tern1(float v, float inv) {
    float r = rintf(v * inv);
    return fminf(1.0f, fmaxf(-1.0f, r));
}

__global__ __launch_bounds__(256) void glu55_tern(const float* __restrict__ w) {
    const int gid = blockIdx.x * 256 + threadIdx.x;
    const float inv = 1.0f / (g55_wgamma + 1e-7f);
    const float4* w4 = reinterpret_cast<const float4*>(w);
    float4 a = w4[gid * 2 + 0];
    float4 b = w4[gid * 2 + 1];
    H8 o;
    o.a = __floats2half2_rn(tern1(a.x, inv), tern1(a.y, inv));
    o.b = __floats2half2_rn(tern1(a.z, inv), tern1(a.w, inv));
    o.c = __floats2half2_rn(tern1(b.x, inv), tern1(b.y, inv));
    o.d = __floats2half2_rn(tern1(b.z, inv), tern1(b.w, inv));
    reinterpret_cast<H8*>(g55_wbin)[gid] = o;
}

__global__ __launch_bounds__(256) void glu55_ln(const float* __restrict__ x) {
    const int row = blockIdx.x;
    const int tid = threadIdx.x;
    const float4* xr = reinterpret_cast<const float4*>(x + (size_t)row * K_DIM);
    float4 v0 = xr[tid * 2 + 0];
    float4 v1 = xr[tid * 2 + 1];
    float s = v0.x + v0.y + v0.z + v0.w + v1.x + v1.y + v1.z + v1.w;
    float q = v0.x * v0.x + v0.y * v0.y + v0.z * v0.z + v0.w * v0.w +
              v1.x * v1.x + v1.y * v1.y + v1.z * v1.z + v1.w * v1.w;
    s = warp_sum(s);
    q = warp_sum(q);
    __shared__ float sh[18];
    const int wid = tid >> 5, lid = tid & 31;
    if (lid == 0) { sh[wid] = s; sh[8 + wid] = q; }
    __syncthreads();
    if (tid == 0) {
        float S = 0.0f, Q = 0.0f;
#pragma unroll
        for (int i = 0; i < 8; ++i) { S += sh[i]; Q += sh[8 + i]; }
        float mu  = S * (1.0f / (float)K_DIM);
        float var = Q * (1.0f / (float)K_DIM) - mu * mu;
        sh[16] = mu;
        sh[17] = rsqrtf(var + 1e-5f);
    }
    __syncthreads();
    const float mu = sh[16], rs = sh[17];
    H8 o;
    o.a = __floats2half2_rn((v0.x - mu) * rs, (v0.y - mu) * rs);
    o.b = __floats2half2_rn((v0.z - mu) * rs, (v0.w - mu) * rs);
    o.c = __floats2half2_rn((v1.x - mu) * rs, (v1.y - mu) * rs);
    o.d = __floats2half2_rn((v1.z - mu) * rs, (v1.w - mu) * rs);
    reinterpret_cast<H8*>(g55_act)[(size_t)row * (K_DIM / 8) + tid] = o;
}

// ======================= persistent GEMM + fused GLU =============
// R2 config: 2 CTAs/SM, 8 warps (wm=wid&3 m32, ngrp=wid>>1... ngrp=wid>>2),
// tile = 128m x 128 B-rows (64 h + 64 g = 64 out cols). Persistent: grid =
// 2*#SM CTAs; each streams ~13.8 tiles through a continuous chunk pipeline
// (stage = g mod 3), epilogue at tile boundaries overlaps in-flight loads.

__global__ void __launch_bounds__(256, 2) glu55_gemm(
    const __half* __restrict__ A, const __half* __restrict__ B,
    float* __restrict__ out)
{
    extern __shared__ char smem[];
    const uint32_t sbase = smem_u32(smem);
    const int tid  = threadIdx.x;
    const int lane = tid & 31;
    const int wid  = tid >> 5;
    const int wm   = wid & 3;
    const int ngrp = wid >> 2;
    const int bid  = blockIdx.x;
    const int grid = gridDim.x;

    const int ntiles = (bid < TOTAL_TILES) ? ((TOTAL_TILES - 1 - bid) / grid + 1) : 0;
    const int total  = ntiles * CHUNKS_PER_TILE;
    if (total == 0) return;

    float ah[2][4][4], ag[2][4][4];
#pragma unroll
    for (int i = 0; i < 2; ++i)
#pragma unroll
        for (int j = 0; j < 4; ++j)
#pragma unroll
            for (int k = 0; k < 4; ++k) { ah[i][j][k] = 0.0f; ag[i][j][k] = 0.0f; }

    const int ld_row = tid >> 3;   // 0..31
    const int ld_ch  = tid & 7;

    auto issue_stage = [&](int g) {
        const int id = bid + (g >> 5) * grid;   // global tile id
        const int mT = id & 63;
        const int nT = id >> 6;
        const int k0 = (g & 31) * BK;
        const uint32_t sA = sbase + (g % NSTAGE) * STAGE_BYTES;
        const uint32_t sB = sA + TILE_BYTES;
        const __half* gAr = A + (size_t)(mT * BM) * K_DIM + k0;
#pragma unroll
        for (int it = 0; it < 4; ++it) {
            const int row = it * 32 + ld_row;
            const __half* src = gAr + (size_t)row * K_DIM + ld_ch * 8;
            CP_ASYNC16(sA + row * 128 + ((ld_ch ^ (row & 7)) << 4), src);
        }
        const __half* gBr = B + (size_t)(nT * 64) * K_DIM + k0;
#pragma unroll
        for (int it = 0; it < 4; ++it) {
            const int row = it * 32 + ld_row;                   // 0..127
            const size_t grow = (size_t)(row & 63) + ((size_t)(row >> 6) << 12); // +4096 = g half
            const __half* src = gBr + grow * K_DIM + ld_ch * 8;
            CP_ASYNC16(sB + row * 128 + ((ld_ch ^ (row & 7)) << 4), src);
        }
        CP_COMMIT();
    };

    auto compute_stage = [&](int st) {
        const uint32_t sA = sbase + st * STAGE_BYTES;
        const uint32_t sB = sA + TILE_BYTES;
#pragma unroll
        for (int kk = 0; kk < 4; ++kk) {
            uint32_t a[2][4];
#pragma unroll
            for (int mt = 0; mt < 2; ++mt) {
                const int row = wm * 32 + mt * 16 + (lane & 15);
                const int ch  = kk * 2 + (lane >> 4);
                LDSM_X4(a[mt][0], a[mt][1], a[mt][2], a[mt][3],
                        sA + row * 128 + ((ch ^ (row & 7)) << 4));
            }
            uint32_t bh[2][4], bg[2][4];
#pragma unroll
            for (int tp = 0; tp < 2; ++tp) {
                const int rb = ngrp * 32 + tp * 16 + ((lane >> 4) << 3) + (lane & 7);
                const int ch = kk * 2 + ((lane >> 3) & 1);
                const uint32_t sw = ((ch ^ (rb & 7)) << 4);
                LDSM_X4(bh[tp][0], bh[tp][1], bh[tp][2], bh[tp][3], sB + rb * 128 + sw);
                LDSM_X4(bg[tp][0], bg[tp][1], bg[tp][2], bg[tp][3], sB + (rb + 64) * 128 + sw);
            }
#pragma unroll
            for (int mt = 0; mt < 2; ++mt)
#pragma unroll
                for (int tp = 0; tp < 2; ++tp) {
                    MMA16816(ah[mt][2 * tp + 0], a[mt][0], a[mt][1], a[mt][2], a[mt][3], bh[tp][0], bh[tp][1]);
                    MMA16816(ah[mt][2 * tp + 1], a[mt][0], a[mt][1], a[mt][2], a[mt][3], bh[tp][2], bh[tp][3]);
                    MMA16816(ag[mt][2 * tp + 0], a[mt][0], a[mt][1], a[mt][2], a[mt][3], bg[tp][0], bg[tp][1]);
                    MMA16816(ag[mt][2 * tp + 1], a[mt][0], a[mt][1], a[mt][2], a[mt][3], bg[tp][2], bg[tp][3]);
                }
        }
    };

    const float gw = g55_wgamma;

    issue_stage(0);
    if (total > 1) issue_stage(1); else CP_COMMIT();

    for (int g = 0; g < total; ++g) {
        CP_WAIT(1);
        __syncthreads();
        // issue BEFORE compute: stage (g+2)%3 == (g-1)%3 was fully consumed
        // before the barrier above; doubles load latency slack.
        if (g + 2 < total) issue_stage(g + 2);
        else CP_COMMIT();
        compute_stage(g % NSTAGE);

        if ((g & 31) == 31) {
            // ---- fused GLU epilogue for tile (g>>5); overlaps in-flight loads ----
            const int id = bid + (g >> 5) * grid;
            const int mT = id & 63;
            const int nT = id >> 6;
            const int row0 = mT * BM + wm * 32 + (lane >> 2);
            const int col0 = nT * 64 + ngrp * 32 + 2 * (lane & 3);
#pragma unroll
            for (int mt = 0; mt < 2; ++mt)
#pragma unroll
                for (int nb = 0; nb < 4; ++nb)
#pragma unroll
                    for (int hf = 0; hf < 2; ++hf) {
                        const float h0 = ah[mt][nb][2 * hf + 0] * gw;
                        const float h1 = ah[mt][nb][2 * hf + 1] * gw;
                        const float g0 = ag[mt][nb][2 * hf + 0] * gw;
                        const float g1 = ag[mt][nb][2 * hf + 1] * gw;
                        float2 o;
                        o.x = h0 * (g0 / (1.0f + __expf(-g0)));
                        o.y = h1 * (g1 / (1.0f + __expf(-g1)));
                        const int r = row0 + mt * 16 + hf * 8;
                        *reinterpret_cast<float2*>(out + (size_t)r * N_OUT + col0 + nb * 8) = o;
                        ah[mt][nb][2 * hf + 0] = 0.0f; ah[mt][nb][2 * hf + 1] = 0.0f;
                        ag[mt][nb][2 * hf + 0] = 0.0f; ag[mt][nb][2 * hf + 1] = 0.0f;
                    }
        }
    }
}

// ======================= host launcher ===========================

extern "C" void kernel_launch(void* const* d_in, const int* in_sizes, int n_in,
                              void* d_out, int out_size) {
    (void)in_sizes; (void)n_in; (void)out_size;
    const float* x = (const float*)d_in[0];
    const float* w = (const float*)d_in[1];
    float* out = (float*)d_out;

    void *p_wbin = nullptr, *p_act = nullptr;
    cudaGetSymbolAddress(&p_wbin, g55_wbin);
    cudaGetSymbolAddress(&p_act,  g55_act);

    glu55_wabs_partial<<<2048, 256>>>(w);
    glu55_wabs_final<<<1, 256>>>();
    glu55_tern<<<8192, 256>>>(w);
    glu55_ln<<<M_TOK, 256>>>(x);

    int nsm = 148;
    cudaDeviceGetAttribute(&nsm, cudaDevAttrMultiProcessorCount, 0);

    cudaFuncSetAttribute(glu55_gemm, cudaFuncAttributeMaxDynamicSharedMemorySize, SMEM_TOTAL);
    glu55_gemm<<<2 * nsm, 256, SMEM_TOTAL>>>(
        (const __half*)p_act, (const __half*)p_wbin, out);
}

// round 7
// speedup vs baseline: 1.2364x; 1.2064x over previous
#include <cuda_runtime.h>
#include <cuda_fp16.h>
#include <cstdint>

// ======================= problem constants =======================
static constexpr int K_DIM  = 2048;
static constexpr int N_ROWS = 8192;
static constexpr int M_TOK  = 8192;
static constexpr int N_OUT  = 4096;

// ======================= GEMM tiling (R2-proven) =================
static constexpr int BM = 128;
static constexpr int BK = 64;
static constexpr int NCHUNK = K_DIM / BK;               // 32
static constexpr int NSTAGE = 3;
static constexpr int TILE_BYTES  = BM * BK * 2;         // 16384
static constexpr int STAGE_BYTES = 2 * TILE_BYTES;      // 32768
static constexpr int SMEM_STAGE0 = 1024;                // barriers live below
static constexpr int SMEM_TOTAL  = SMEM_STAGE0 + NSTAGE * STAGE_BYTES;  // 99328

// ======================= device scratch ==========================
__device__ float  g55_partial[2048];
__device__ float  g55_wgamma;
__device__ __half g55_wbin[(size_t)N_ROWS * K_DIM];
__device__ __half g55_act [(size_t)M_TOK  * K_DIM];

struct __align__(16) H8 { __half2 a, b, c, d; };

// ======================= asm helpers =============================
__device__ __forceinline__ uint32_t smem_u32(const void* p) {
    uint32_t a;
    asm("{ .reg .u64 t; cvta.to.shared.u64 t, %1; cvt.u32.u64 %0, t; }" : "=r"(a) : "l"(p));
    return a;
}

#define CP_ASYNC16(dst_u32, src_ptr) \
    asm volatile("cp.async.cg.shared.global [%0], [%1], 16;" \
                 :: "r"(dst_u32), "l"(src_ptr) : "memory")

#define CP_ASYNC_ARRIVE(mbar) \
    asm volatile("cp.async.mbarrier.arrive.noinc.shared.b64 [%0];" \
                 :: "r"((uint32_t)(mbar)) : "memory")

#define MBARRIER_INIT(addr, count) \
    asm volatile("mbarrier.init.shared.b64 [%0], %1;" \
                 :: "r"((uint32_t)(addr)), "r"((uint32_t)(count)) : "memory")

#define MBARRIER_ARRIVE(addr) \
    asm volatile("mbarrier.arrive.shared.b64 _, [%0];" \
                 :: "r"((uint32_t)(addr)) : "memory")

#define MBARRIER_WAIT_PARITY(addr, parity) do {                                     \
    uint32_t _m = (uint32_t)(addr);                                                 \
    uint32_t _p = (uint32_t)(parity);                                               \
    asm volatile(                                                                   \
        "{\n\t.reg .pred P1;\n\t"                                                   \
        "WAIT_LOOP_%=:\n\t"                                                         \
        "mbarrier.try_wait.parity.shared.b64 P1, [%0], %1;\n\t"                     \
        "@P1 bra.uni WAIT_DONE_%=;\n\t"                                             \
        "bra.uni WAIT_LOOP_%=;\n\t"                                                 \
        "WAIT_DONE_%=:\n\t}"                                                        \
        :: "r"(_m), "r"(_p) : "memory");                                            \
} while (0)

#define LDSM_X4(r0, r1, r2, r3, addr) \
    asm volatile("ldmatrix.sync.aligned.m8n8.x4.shared.b16 {%0,%1,%2,%3}, [%4];" \
                 : "=r"(r0), "=r"(r1), "=r"(r2), "=r"(r3) : "r"(addr))

#define MMA16816(d, a0, a1, a2, a3, b0, b1) \
    asm volatile("mma.sync.aligned.m16n8k16.row.col.f32.f16.f16.f32 " \
                 "{%0,%1,%2,%3}, {%4,%5,%6,%7}, {%8,%9}, {%0,%1,%2,%3};" \
                 : "+f"((d)[0]), "+f"((d)[1]), "+f"((d)[2]), "+f"((d)[3]) \
                 : "r"(a0), "r"(a1), "r"(a2), "r"(a3), "r"(b0), "r"(b1))

__device__ __forceinline__ float warp_sum(float v) {
#pragma unroll
    for (int o = 16; o; o >>= 1) v += __shfl_xor_sync(0xffffffffu, v, o);
    return v;
}

// ======================= prep kernels (R2 proven, unchanged) ======

__global__ __launch_bounds__(256) void glu55_wabs_partial(const float* __restrict__ w) {
    const int tid = threadIdx.x;
    const float4* w4 = reinterpret_cast<const float4*>(w);
    float s = 0.0f;
    int idx = blockIdx.x * 256 + tid;
#pragma unroll
    for (int i = 0; i < 8; ++i) {
        float4 v = w4[idx + i * (2048 * 256)];
        s += fabsf(v.x) + fabsf(v.y) + fabsf(v.z) + fabsf(v.w);
    }
    s = warp_sum(s);
    __shared__ float sh[8];
    if ((tid & 31) == 0) sh[tid >> 5] = s;
    __syncthreads();
    if (tid == 0) {
        float t = 0.0f;
#pragma unroll
        for (int i = 0; i < 8; ++i) t += sh[i];
        g55_partial[blockIdx.x] = t;
    }
}

__global__ __launch_bounds__(256) void glu55_wabs_final() {
    const int tid = threadIdx.x;
    float s = 0.0f;
    for (int i = tid; i < 2048; i += 256) s += g55_partial[i];
    s = warp_sum(s);
    __shared__ float sh[8];
    if ((tid & 31) == 0) sh[tid >> 5] = s;
    __syncthreads();
    if (tid == 0) {
        float t = 0.0f;
#pragma unroll
        for (int i = 0; i < 8; ++i) t += sh[i];
        g55_wgamma = t / (float)((size_t)N_ROWS * K_DIM);
    }
}

__device__ __forceinline__ float tern1(float v, float inv) {
    float r = rintf(v * inv);
    return fminf(1.0f, fmaxf(-1.0f, r));
}

__global__ __launch_bounds__(256) void glu55_tern(const float* __restrict__ w) {
    const int gid = blockIdx.x * 256 + threadIdx.x;
    const float inv = 1.0f / (g55_wgamma + 1e-7f);
    const float4* w4 = reinterpret_cast<const float4*>(w);
    float4 a = w4[gid * 2 + 0];
    float4 b = w4[gid * 2 + 1];
    H8 o;
    o.a = __floats2half2_rn(tern1(a.x, inv), tern1(a.y, inv));
    o.b = __floats2half2_rn(tern1(a.z, inv), tern1(a.w, inv));
    o.c = __floats2half2_rn(tern1(b.x, inv), tern1(b.y, inv));
    o.d = __floats2half2_rn(tern1(b.z, inv), tern1(b.w, inv));
    reinterpret_cast<H8*>(g55_wbin)[gid] = o;
}

__global__ __launch_bounds__(256) void glu55_ln(const float* __restrict__ x) {
    const int row = blockIdx.x;
    const int tid = threadIdx.x;
    const float4* xr = reinterpret_cast<const float4*>(x + (size_t)row * K_DIM);
    float4 v0 = xr[tid * 2 + 0];
    float4 v1 = xr[tid * 2 + 1];
    float s = v0.x + v0.y + v0.z + v0.w + v1.x + v1.y + v1.z + v1.w;
    float q = v0.x * v0.x + v0.y * v0.y + v0.z * v0.z + v0.w * v0.w +
              v1.x * v1.x + v1.y * v1.y + v1.z * v1.z + v1.w * v1.w;
    s = warp_sum(s);
    q = warp_sum(q);
    __shared__ float sh[18];
    const int wid = tid >> 5, lid = tid & 31;
    if (lid == 0) { sh[wid] = s; sh[8 + wid] = q; }
    __syncthreads();
    if (tid == 0) {
        float S = 0.0f, Q = 0.0f;
#pragma unroll
        for (int i = 0; i < 8; ++i) { S += sh[i]; Q += sh[8 + i]; }
        float mu  = S * (1.0f / (float)K_DIM);
        float var = Q * (1.0f / (float)K_DIM) - mu * mu;
        sh[16] = mu;
        sh[17] = rsqrtf(var + 1e-5f);
    }
    __syncthreads();
    const float mu = sh[16], rs = sh[17];
    H8 o;
    o.a = __floats2half2_rn((v0.x - mu) * rs, (v0.y - mu) * rs);
    o.b = __floats2half2_rn((v0.z - mu) * rs, (v0.w - mu) * rs);
    o.c = __floats2half2_rn((v1.x - mu) * rs, (v1.y - mu) * rs);
    o.d = __floats2half2_rn((v1.z - mu) * rs, (v1.w - mu) * rs);
    reinterpret_cast<H8*>(g55_act)[(size_t)row * (K_DIM / 8) + tid] = o;
}

// ======================= GEMM + fused GLU (elastic mbarrier) =====
// R2 config: 4096 CTAs (1 tile each), 2 CTAs/SM, 8 warps (4 wm x 2 ngrp).
// Pipeline: 3 stages; full[s] fires when all 256 threads' cp.asyncs land
// (cp.async.mbarrier.arrive.noinc); empty[s] fires when all 8 warps have
// consumed the stage. No __syncthreads / wait_group in the main loop ->
// warps drift instead of lockstepping 32x per tile.

__global__ void __launch_bounds__(256, 2) glu55_gemm(
    const __half* __restrict__ A, const __half* __restrict__ B,
    float* __restrict__ out)
{
    extern __shared__ char smem[];
    const uint32_t sbase = smem_u32(smem);
    const uint32_t mb_full  = sbase;        // 3 x 8B
    const uint32_t mb_empty = sbase + 24;   // 3 x 8B
    const uint32_t stage0   = sbase + SMEM_STAGE0;
    const int tid  = threadIdx.x;
    const int lane = tid & 31;
    const int wid  = tid >> 5;
    const int wm   = wid & 3;
    const int ngrp = wid >> 2;
    const int mTile = blockIdx.x & 63;   // consecutive blocks share B tile (L2 reuse)
    const int nTile = blockIdx.x >> 6;

    if (tid == 0) {
#pragma unroll
        for (int s = 0; s < NSTAGE; ++s) {
            MBARRIER_INIT(mb_full  + 8 * s, 256);
            MBARRIER_INIT(mb_empty + 8 * s, 8);
        }
    }
    __syncthreads();

    const __half* gA = A + (size_t)mTile * BM * K_DIM;

    float ah[2][4][4], ag[2][4][4];
#pragma unroll
    for (int i = 0; i < 2; ++i)
#pragma unroll
        for (int j = 0; j < 4; ++j)
#pragma unroll
            for (int k = 0; k < 4; ++k) { ah[i][j][k] = 0.0f; ag[i][j][k] = 0.0f; }

    const int ld_row = tid >> 3;   // 0..31
    const int ld_ch  = tid & 7;

    auto issue_stage = [&](int g) {
        const int st = g % NSTAGE;
        const int k0 = g * BK;
        const uint32_t sA = stage0 + st * STAGE_BYTES;
        const uint32_t sB = sA + TILE_BYTES;
#pragma unroll
        for (int it = 0; it < 4; ++it) {
            const int row = it * 32 + ld_row;
            const __half* src = gA + (size_t)row * K_DIM + k0 + ld_ch * 8;
            CP_ASYNC16(sA + row * 128 + ((ld_ch ^ (row & 7)) << 4), src);
        }
        const __half* gBr = B + (size_t)(nTile * 64) * K_DIM + k0;
#pragma unroll
        for (int it = 0; it < 4; ++it) {
            const int row = it * 32 + ld_row;                   // 0..127
            const size_t grow = (size_t)(row & 63) + ((size_t)(row >> 6) << 12); // +4096 = g half
            const __half* src = gBr + grow * K_DIM + ld_ch * 8;
            CP_ASYNC16(sB + row * 128 + ((ld_ch ^ (row & 7)) << 4), src);
        }
        CP_ASYNC_ARRIVE(mb_full + 8 * st);
    };

    auto compute_stage = [&](int st) {
        const uint32_t sA = stage0 + st * STAGE_BYTES;
        const uint32_t sB = sA + TILE_BYTES;
#pragma unroll
        for (int kk = 0; kk < 4; ++kk) {
            uint32_t a[2][4];
#pragma unroll
            for (int mt = 0; mt < 2; ++mt) {
                const int row = wm * 32 + mt * 16 + (lane & 15);
                const int ch  = kk * 2 + (lane >> 4);
                LDSM_X4(a[mt][0], a[mt][1], a[mt][2], a[mt][3],
                        sA + row * 128 + ((ch ^ (row & 7)) << 4));
            }
            uint32_t bh[2][4], bg[2][4];
#pragma unroll
            for (int tp = 0; tp < 2; ++tp) {
                const int rb = ngrp * 32 + tp * 16 + ((lane >> 4) << 3) + (lane & 7);
                const int ch = kk * 2 + ((lane >> 3) & 1);
                const uint32_t sw = ((ch ^ (rb & 7)) << 4);
                LDSM_X4(bh[tp][0], bh[tp][1], bh[tp][2], bh[tp][3], sB + rb * 128 + sw);
                LDSM_X4(bg[tp][0], bg[tp][1], bg[tp][2], bg[tp][3], sB + (rb + 64) * 128 + sw);
            }
#pragma unroll
            for (int mt = 0; mt < 2; ++mt)
#pragma unroll
                for (int tp = 0; tp < 2; ++tp) {
                    MMA16816(ah[mt][2 * tp + 0], a[mt][0], a[mt][1], a[mt][2], a[mt][3], bh[tp][0], bh[tp][1]);
                    MMA16816(ah[mt][2 * tp + 1], a[mt][0], a[mt][1], a[mt][2], a[mt][3], bh[tp][2], bh[tp][3]);
                    MMA16816(ag[mt][2 * tp + 0], a[mt][0], a[mt][1], a[mt][2], a[mt][3], bg[tp][0], bg[tp][1]);
                    MMA16816(ag[mt][2 * tp + 1], a[mt][0], a[mt][1], a[mt][2], a[mt][3], bg[tp][2], bg[tp][3]);
                }
        }
    };

    issue_stage(0);
    issue_stage(1);

#pragma unroll 1
    for (int g = 0; g < NCHUNK; ++g) {
        const int st = g % NSTAGE;
        MBARRIER_WAIT_PARITY(mb_full + 8 * st, (g / NSTAGE) & 1);
        compute_stage(st);
        if (lane == 0) MBARRIER_ARRIVE(mb_empty + 8 * st);
        const int gg = g + 2;
        if (gg < NCHUNK) {
            const int st2 = gg % NSTAGE;
            if (gg >= NSTAGE)
                MBARRIER_WAIT_PARITY(mb_empty + 8 * st2, ((gg / NSTAGE) - 1) & 1);
            issue_stage(gg);
        }
    }

    // ---- fused GLU epilogue (all in registers) ----
    const float gw = g55_wgamma;
    const int row0 = mTile * BM + wm * 32 + (lane >> 2);
    const int col0 = nTile * 64 + ngrp * 32 + 2 * (lane & 3);
#pragma unroll
    for (int mt = 0; mt < 2; ++mt)
#pragma unroll
        for (int nb = 0; nb < 4; ++nb)
#pragma unroll
            for (int hf = 0; hf < 2; ++hf) {
                const float h0 = ah[mt][nb][2 * hf + 0] * gw;
                const float h1 = ah[mt][nb][2 * hf + 1] * gw;
                const float g0 = ag[mt][nb][2 * hf + 0] * gw;
                const float g1 = ag[mt][nb][2 * hf + 1] * gw;
                float2 o;
                o.x = h0 * (g0 / (1.0f + __expf(-g0)));
                o.y = h1 * (g1 / (1.0f + __expf(-g1)));
                const int r = row0 + mt * 16 + hf * 8;
                *reinterpret_cast<float2*>(out + (size_t)r * N_OUT + col0 + nb * 8) = o;
            }
}

// ======================= host launcher ===========================

extern "C" void kernel_launch(void* const* d_in, const int* in_sizes, int n_in,
                              void* d_out, int out_size) {
    (void)in_sizes; (void)n_in; (void)out_size;
    const float* x = (const float*)d_in[0];
    const float* w = (const float*)d_in[1];
    float* out = (float*)d_out;

    void *p_wbin = nullptr, *p_act = nullptr;
    cudaGetSymbolAddress(&p_wbin, g55_wbin);
    cudaGetSymbolAddress(&p_act,  g55_act);

    glu55_wabs_partial<<<2048, 256>>>(w);
    glu55_wabs_final<<<1, 256>>>();
    glu55_tern<<<8192, 256>>>(w);
    glu55_ln<<<M_TOK, 256>>>(x);

    cudaFuncSetAttribute(glu55_gemm, cudaFuncAttributeMaxDynamicSharedMemorySize, SMEM_TOTAL);
    glu55_gemm<<<(M_TOK / BM) * (N_OUT / 64), 256, SMEM_TOTAL>>>(
        (const __half*)p_act, (const __half*)p_wbin, out);
}